// round 10
// baseline (speedup 1.0000x reference)
#include <cuda_runtime.h>
#include <cuda_bf16.h>

#define BATCH 64
#define FDIM 768     // 3 * 16 * 16
#define DDIM 128
#define KCLS 1000

// Scratch (no allocations allowed in kernel_launch)
__device__ float g_scratch[BATCH * FDIM];     // per-batch global-mean patch vector
__device__ float root_scratch[BATCH * DDIM];  // root token per batch

// ---------------------------------------------------------------------------
// K1: g[b, c*256 + pi*16 + pj] = (1/256) * sum_{h,w} x[b,c,16h+pi,16w+pj]
//
// One block per (b,c) plane: 192 blocks x 512 threads. The plane is 256 rows
// x 64 float4 = 16384 float4, read as a contiguous grid-stride: thread t
// loads f4 index t + 512*k, k = 0..31. Since 512 f4 == exactly 8 rows:
//   - the column index (i = t & 63) is CONSTANT across k
//   - the row is row0 + 8k, so pi = row & 15 alternates row0 / row0+8
// => each thread folds its 32 loads into two float4 accumulators (4 used for
// ILP), and the (pi,pj) 16x16 reduction completes in one shared pass.
// Warp requests are sequential 512B chunks -> maximal DRAM row locality.
// ---------------------------------------------------------------------------
__global__ void __launch_bounds__(512)
reduce_patches_kernel(const float* __restrict__ x) {
    int blk = blockIdx.x;            // b*3 + c
    int b   = blk / 3;
    int c   = blk % 3;
    int t   = threadIdx.x;           // 0..511
    int row0 = t >> 6;               // 0..7
    int i    = t & 63;               // f4 column within row (constant over k)

    const float4* base = reinterpret_cast<const float4*>(
        x + ((size_t)(b * 3 + c) << 16));

    float4 a0 = make_float4(0.f,0.f,0.f,0.f);
    float4 a1 = make_float4(0.f,0.f,0.f,0.f);
    float4 a2 = make_float4(0.f,0.f,0.f,0.f);
    float4 a3 = make_float4(0.f,0.f,0.f,0.f);

    #pragma unroll
    for (int k = 0; k < 32; k += 4) {   // 4 independent chains -> high MLP
        float4 v0 = base[t + 512 * (k + 0)];   // pi = row0
        float4 v1 = base[t + 512 * (k + 1)];   // pi = row0 + 8
        float4 v2 = base[t + 512 * (k + 2)];   // pi = row0
        float4 v3 = base[t + 512 * (k + 3)];   // pi = row0 + 8
        a0.x += v0.x; a0.y += v0.y; a0.z += v0.z; a0.w += v0.w;
        a1.x += v1.x; a1.y += v1.y; a1.z += v1.z; a1.w += v1.w;
        a2.x += v2.x; a2.y += v2.y; a2.z += v2.z; a2.w += v2.w;
        a3.x += v3.x; a3.y += v3.y; a3.z += v3.z; a3.w += v3.w;
    }
    float4 accE = make_float4(a0.x + a2.x, a0.y + a2.y, a0.z + a2.z, a0.w + a2.w);
    float4 accO = make_float4(a1.x + a3.x, a1.y + a3.y, a1.z + a3.z, a1.w + a3.w);

    // s4[pi][pjg][islot], islot padded 16->17 for conflict-free scalar reads
    __shared__ __align__(16) float4 s4[16][4][17];   // 17408 B
    int pjg   = i & 3;       // pj group: f4 at col 4i covers pj = 4*(i&3)..+3
    int islot = i >> 2;      // 0..15: which of the 16 f4-columns mapping to pjg
    s4[row0    ][pjg][islot] = accE;
    s4[row0 + 8][pjg][islot] = accO;
    __syncthreads();

    // 256 reducer threads: one per (pi, pj)
    if (t < 256) {
        int pi = t >> 4;
        int pj = t & 15;
        int pg = pj >> 2;
        int cp = pj & 3;
        const float* sf = reinterpret_cast<const float*>(s4);
        // float offset = ((pi*4 + pg)*17 + islot)*4 + cp  -> distinct banks/warp
        int basef = ((pi * 4 + pg) * 17) * 4 + cp;
        float sum = 0.0f;
        #pragma unroll
        for (int sl = 0; sl < 16; ++sl)
            sum += sf[basef + sl * 4];
        g_scratch[b * FDIM + c * 256 + pi * 16 + pj] = sum * (1.0f / 256.0f);
    }
}

// ---------------------------------------------------------------------------
// K2: root[b,d] = dot(W_emb[d,:], g[b,:]) + b_emb[d] + pos4[d]
// Grid: (128 d, 2 b-halves) = 256 blocks, 256 threads = 32 b x 8 segments.
// ---------------------------------------------------------------------------
__global__ void embed_root_kernel(const float* __restrict__ W_emb,
                                  const float* __restrict__ b_emb,
                                  const float* __restrict__ pos4) {
    int d    = blockIdx.x;           // 0..127
    int half = blockIdx.y;           // 0..1
    int t    = threadIdx.x;
    int b    = half * 32 + (t >> 3);
    int seg  = t & 7;

    __shared__ __align__(16) float w_sh[FDIM];
    for (int i = t; i < FDIM; i += 256)
        w_sh[i] = W_emb[(size_t)d * FDIM + i];
    __syncthreads();

    const float4* g4 = reinterpret_cast<const float4*>(g_scratch + (size_t)b * FDIM);
    const float4* w4 = reinterpret_cast<const float4*>(w_sh);

    float acc = 0.0f;
    #pragma unroll
    for (int i = 0; i < 24; ++i) {
        int f4 = i * 8 + seg;
        float4 g = g4[f4];
        float4 w = w4[f4];
        acc += w.x * g.x + w.y * g.y + w.z * g.z + w.w * g.w;
    }
    acc += __shfl_xor_sync(0xFFFFFFFFu, acc, 1);
    acc += __shfl_xor_sync(0xFFFFFFFFu, acc, 2);
    acc += __shfl_xor_sync(0xFFFFFFFFu, acc, 4);

    if (seg == 0)
        root_scratch[b * DDIM + d] = acc + b_emb[d] + pos4[d];
}

// ---------------------------------------------------------------------------
// K3: logits[b,k] = dot(W_cls[k,:], root[b,:]) + b_cls[k]
// Grid: 250 blocks (4 classes each), 256 threads = 64 b x 4 k.
// ---------------------------------------------------------------------------
#define RPAD 132

__global__ void classify_kernel(const float* __restrict__ W_cls,
                                const float* __restrict__ b_cls,
                                float* __restrict__ out) {
    int kbase = blockIdx.x * 4;
    int t = threadIdx.x;

    __shared__ __align__(16) float r_sh[BATCH * RPAD];  // 33792 B
    __shared__ __align__(16) float w_sh[4 * RPAD];      //  2112 B

    {
        const float4* src = reinterpret_cast<const float4*>(root_scratch);
        for (int idx = t; idx < BATCH * (DDIM / 4); idx += 256) {
            int b  = idx >> 5;
            int i4 = idx & 31;
            *reinterpret_cast<float4*>(&r_sh[b * RPAD + i4 * 4]) = src[idx];
        }
    }
    {
        const float4* src = reinterpret_cast<const float4*>(W_cls + (size_t)kbase * DDIM);
        for (int idx = t; idx < 4 * (DDIM / 4); idx += 256) {
            int k  = idx >> 5;
            int i4 = idx & 31;
            *reinterpret_cast<float4*>(&w_sh[k * RPAD + i4 * 4]) = src[idx];
        }
    }
    __syncthreads();

    int b = t >> 2;
    int k = t & 3;
    const float4* r4 = reinterpret_cast<const float4*>(&r_sh[b * RPAD]);
    const float4* w4 = reinterpret_cast<const float4*>(&w_sh[k * RPAD]);

    float acc = 0.0f;
    #pragma unroll
    for (int i = 0; i < DDIM / 4; ++i) {
        float4 w = w4[i];
        float4 r = r4[i];
        acc += w.x * r.x + w.y * r.y + w.z * r.z + w.w * r.w;
    }
    out[b * KCLS + kbase + k] = acc + b_cls[kbase + k];
}

// ---------------------------------------------------------------------------
// Inputs (metadata order):
//   0: x (64,3,256,256)   1: W_emb (128,768)   2: b_emb (128)
//   3..7: pos0..pos4      8: W_cls (1000,128)  9: b_cls (1000)
// Output: logits (64,1000) float32
// Only x, W_emb, b_emb, pos4, W_cls, b_cls are live (levels 0-3 and pos0-3
// are dead code in the reference: output uses only the global-mean level).
// ---------------------------------------------------------------------------
extern "C" void kernel_launch(void* const* d_in, const int* in_sizes, int n_in,
                              void* d_out, int out_size) {
    const float* x     = (const float*)d_in[0];
    const float* W_emb = (const float*)d_in[1];
    const float* b_emb = (const float*)d_in[2];
    const float* pos4  = (const float*)d_in[7];
    const float* W_cls = (const float*)d_in[8];
    const float* b_cls = (const float*)d_in[9];
    float* out = (float*)d_out;

    reduce_patches_kernel<<<BATCH * 3, 512>>>(x);
    embed_root_kernel<<<dim3(DDIM, 2), 256>>>(W_emb, b_emb, pos4);
    classify_kernel<<<KCLS / 4, 256>>>(W_cls, b_cls, out);
}